// round 15
// baseline (speedup 1.0000x reference)
#include <cuda_runtime.h>
#include <math.h>

#define BB 2
#define NN 512
#define CC 256
#define OUTSZ 14
#define POOL_PER_BOX (CC * OUTSZ * OUTSZ)   // 50176
#define NPOS (OUTSZ * OUTSZ)                // 196
#define CQ 64                               // channels per pool block (4-way split)
#define NCH 4                               // channels per phase (float4 interleave)
#define NPH (CQ / NCH)                      // 16 phases
#define PSZ 1024                            // patch elems per channel (worst ~991)

// Scratch (no allocations allowed)
__device__ float g_verts[BB * NN * 4];      // original order
__device__ int   g_level[BB * NN];          // original order
__device__ int   g_keep [BB * NN];          // original order

// ---------------------------------------------------------------------------
// Kernel 1: fully fused NMS. Grid = BB, 512 threads (16 warps).
//   counting-rank stable sort -> ballot mask build (16 warps x 32 rows)
//   -> single-warp ffs greedy scan -> keep/out_boxes tail writes.
// ---------------------------------------------------------------------------
__global__ __launch_bounds__(NN) void nms_kernel(const float* __restrict__ boxes,
                                                 const float* __restrict__ scores,
                                                 float* __restrict__ out)
{
    const int b    = blockIdx.x;
    const int tid  = threadIdx.x;
    const int wid  = tid >> 5;
    const int lane = tid & 31;

    __shared__ float         sscore[NN];
    __shared__ float4        sbox[NN];       // sorted order
    __shared__ float         sarea[NN];
    __shared__ unsigned char slev[NN];
    __shared__ short         sord[NN];       // sorted rank -> original idx
    __shared__ unsigned      smask[NN][16];  // 32 KB suppression matrix
    __shared__ unsigned      keepw_s[16];

    // --- verts + level ---
    const float* bbp = boxes + (size_t)b * NN * 4;
    float cx = bbp[tid * 4 + 0];
    float cy = bbp[tid * 4 + 1];
    float w  = bbp[tid * 4 + 2];
    float h  = bbp[tid * 4 + 3];
    float x1 = cx - w * 0.5f;
    float y1 = cy - h * 0.5f;
    float x2 = cx + w * 0.5f;
    float y2 = cy + h * 0.5f;

    float lv = floorf(3.0f + log2f(sqrtf(w * h) / 224.0f));
    lv = fminf(fmaxf(lv, 1.0f), 4.0f);
    int lev = (int)lv;

    int gi = b * NN + tid;
    g_verts[gi * 4 + 0] = x1;
    g_verts[gi * 4 + 1] = y1;
    g_verts[gi * 4 + 2] = x2;
    g_verts[gi * 4 + 3] = y2;
    g_level[gi] = lev;

    float ms = scores[gi];
    sscore[tid] = ms;
    __syncthreads();

    // --- stable descending rank by counting ---
    int r = 0;
    #pragma unroll 8
    for (int j = 0; j < NN; j++) {
        float sj = sscore[j];
        r += (sj > ms) || (sj == ms && j < tid);
    }

    sbox [r] = make_float4(x1, y1, x2, y2);
    sarea[r] = (x2 - x1) * (y2 - y1);
    slev [r] = (unsigned char)lev;
    sord [r] = (short)tid;
    __syncthreads();

    // --- mask build: warp per row, 32 rows per warp (interleaved) ---
    // Division-free IoU test (thr = 0.5): 2*inter > den.
    #pragma unroll 1
    for (int i = 0; i < 32; i++) {
        const int row = wid + (i << 4);     // rows wid, wid+16, ..., wid+496
        float4 mb = sbox[row];
        float  marea = sarea[row];
        unsigned char mylev = slev[row];

        #pragma unroll
        for (int wq = 0; wq < 16; wq++) {
            int j = (wq << 5) + lane;
            float4 ob = sbox[j];
            float ix1 = fmaxf(mb.x, ob.x);
            float iy1 = fmaxf(mb.y, ob.y);
            float ix2 = fminf(mb.z, ob.z);
            float iy2 = fminf(mb.w, ob.w);
            float iw = fmaxf(ix2 - ix1, 0.0f);
            float ih = fmaxf(iy2 - iy1, 0.0f);
            float inter = iw * ih;
            float den = marea + sarea[j] - inter + 1e-9f;
            bool sup = (j > row) && (slev[j] == mylev) && (inter + inter > den);
            unsigned word = __ballot_sync(0xffffffffu, sup);
            if (lane == wq) smask[row][wq] = word;
        }
    }
    __syncthreads();

    // --- greedy scan: single warp, ffs-skip over kept boxes ---
    if (tid < 32) {
        int wl = tid & 15;
        unsigned kw = 0xFFFFFFFFu;
        for (int wq = 0; wq < 16; wq++) {
            unsigned cur = __shfl_sync(0xffffffffu, kw, wq);
            while (cur) {
                int bq = __ffs(cur) - 1;
                int row = (wq << 5) + bq;
                unsigned mw = smask[row][wl];   // broadcast LDS
                unsigned mq = smask[row][wq];   // broadcast LDS
                cur &= ~(mq | (1u << bq));
                kw  &= ~mw;
            }
        }
        if (tid < 16) keepw_s[tid] = kw;
    }
    __syncthreads();

    // --- keep + tail writes (tid is a sorted rank here) ---
    int kept = (keepw_s[tid >> 5] >> (tid & 31)) & 1;
    int o   = sord[tid];
    int go  = b * NN + o;
    g_keep[go] = kept;

    float4 sb = sbox[tid];
    float* ob = out + (size_t)BB * NN * POOL_PER_BOX;
    float* ok = ob + (size_t)BB * NN * 4;
    ob[go * 4 + 0] = kept ? sb.x : 0.0f;
    ob[go * 4 + 1] = kept ? sb.y : 0.0f;
    ob[go * 4 + 2] = kept ? sb.z : 0.0f;
    ob[go * 4 + 3] = kept ? sb.w : 0.0f;
    ok[go] = kept ? 1.0f : 0.0f;
}

// ---------------------------------------------------------------------------
// cp.async helpers
// ---------------------------------------------------------------------------
__device__ __forceinline__ void cpa4(unsigned dst_smem, const float* src) {
    asm volatile("cp.async.ca.shared.global [%0], [%1], 4;"
                 :: "r"(dst_smem), "l"(src) : "memory");
}
__device__ __forceinline__ void cpa_commit() {
    asm volatile("cp.async.commit_group;" ::: "memory");
}
__device__ __forceinline__ void cpa_wait0() {
    asm volatile("cp.async.wait_group 0;" ::: "memory");
}

// ---------------------------------------------------------------------------
// Kernel P: ROI align. Patch channel-interleaved as float4 (4 channels per
// index) -> each tap is one LDS.128 serving 4 channels. 4 blocks per box
// (64 channels each), double-buffered cp.async, one sync per phase.
// (Byte-identical to R14 — proven 182 us.)
// ---------------------------------------------------------------------------
__global__ __launch_bounds__(256, 4) void pool_kernel(const float* __restrict__ p4,
                                                      const float* __restrict__ p8,
                                                      const float* __restrict__ p16,
                                                      const float* __restrict__ p32,
                                                      float* __restrict__ out)
{
    const int bn      = blockIdx.x >> 2;
    const int quarter = blockIdx.x & 3;
    const int b       = bn / NN;
    const int tid     = threadIdx.x;

    float* o = out + (size_t)bn * POOL_PER_BOX + (size_t)quarter * CQ * NPOS;

    if (!g_keep[bn]) {
        float4* o4 = (float4*)o;
        float4 z = make_float4(0.f, 0.f, 0.f, 0.f);
        #pragma unroll 4
        for (int i = tid; i < CQ * NPOS / 4; i += 256) o4[i] = z;
        return;
    }

    const int lev = g_level[bn];
    const float* feat;
    int H;
    float stride;
    if (lev == 1)      { feat = p4;  H = 256; stride = 4.0f;  }
    else if (lev == 2) { feat = p8;  H = 128; stride = 8.0f;  }
    else if (lev == 3) { feat = p16; H = 64;  stride = 16.0f; }
    else               { feat = p32; H = 32;  stride = 32.0f; }
    const int W  = H;
    const int HW = H * W;

    float inv = 1.0f / stride;
    float rx1 = g_verts[bn * 4 + 0] * inv;
    float ry1 = g_verts[bn * 4 + 1] * inv;
    float rx2 = g_verts[bn * 4 + 2] * inv;
    float ry2 = g_verts[bn * 4 + 3] * inv;
    float bw = (rx2 - rx1) / (float)OUTSZ;
    float bh = (ry2 - ry1) / (float)OUTSZ;

    float xsf = fminf(fmaxf(rx1 + 0.25f  * bw, 0.0f), (float)W - 1.0f);
    float xsl = fminf(fmaxf(rx1 + 13.75f * bw, 0.0f), (float)W - 1.0f);
    float ysf = fminf(fmaxf(ry1 + 0.25f  * bh, 0.0f), (float)H - 1.0f);
    float ysl = fminf(fmaxf(ry1 + 13.75f * bh, 0.0f), (float)H - 1.0f);
    const int xmin  = (int)floorf(xsf);
    const int xmax  = min((int)floorf(xsl) + 1, W - 1);
    const int ymin  = (int)floorf(ysf);
    const int ymax  = min((int)floorf(ysl) + 1, H - 1);
    const int pcols = xmax - xmin + 1;
    const int prows = ymax - ymin + 1;
    const int pp    = prows * pcols;

    const int oy = (tid < NPOS) ? (tid / OUTSZ) : 0;
    const int ox = (tid < NPOS) ? (tid - oy * OUTSZ) : 0;

    int   rxo[4];
    float wx[4];
    #pragma unroll
    for (int j = 0; j < 2; j++) {
        float g  = ((float)(2 * ox + j) + 0.5f) * 0.5f;
        float xs = fminf(fmaxf(rx1 + g * bw, 0.0f), (float)W - 1.0f);
        float x0f = floorf(xs);
        int   x0  = (int)x0f;
        float lx  = xs - x0f;
        rxo[2 * j]     = x0;
        rxo[2 * j + 1] = min(x0 + 1, W - 1);
        wx[2 * j]      = 1.0f - lx;
        wx[2 * j + 1]  = lx;
    }
    int   ryo[4];
    float wy[4];
    #pragma unroll
    for (int j = 0; j < 2; j++) {
        float g  = ((float)(2 * oy + j) + 0.5f) * 0.5f;
        float ys = fminf(fmaxf(ry1 + g * bh, 0.0f), (float)H - 1.0f);
        float y0f = floorf(ys);
        int   y0  = (int)y0f;
        float ly  = ys - y0f;
        ryo[2 * j]     = y0;
        ryo[2 * j + 1] = min(y0 + 1, H - 1);
        wy[2 * j]      = 0.25f * (1.0f - ly);
        wy[2 * j + 1]  = 0.25f * ly;
    }

    const float* fp0 = feat + ((size_t)b * CC + (size_t)quarter * CQ) * HW;
    float* op = o + tid;

    if (pp <= PSZ) {
        __shared__ float4 patch[2][PSZ];

        #pragma unroll
        for (int k = 0; k < 4; k++) {
            rxo[k] -= xmin;
            ryo[k] = (ryo[k] - ymin) * pcols;
        }

        int so[4];
        #pragma unroll
        for (int s = 0; s < 4; s++) {
            int i = tid + s * 256;
            int py = i / pcols;
            int px = i - py * pcols;
            so[s] = py * W + px;
        }
        const int nslot = (pp > tid) ? ((pp - tid + 255) >> 8) : 0;
        const float* fb = fp0 + (size_t)ymin * W + xmin;
        const unsigned spbase = (unsigned)__cvta_generic_to_shared(&patch[0][0]);

        #pragma unroll
        for (int ch = 0; ch < NCH; ch++) {
            const float* gch = fb + (size_t)ch * HW;
            #pragma unroll
            for (int s = 0; s < 4; s++)
                if (s < nslot)
                    cpa4(spbase + (unsigned)(tid + s * 256) * 16u + ch * 4u, gch + so[s]);
        }
        cpa_commit();

        #pragma unroll 1
        for (int ph = 0; ph < NPH; ph++) {
            const int buf = ph & 1;
            cpa_wait0();
            __syncthreads();

            if (ph + 1 < NPH) {
                const float* fbn = fb + (size_t)(ph + 1) * NCH * HW;
                unsigned db = spbase + (unsigned)(buf ^ 1) * (PSZ * 16u);
                #pragma unroll
                for (int ch = 0; ch < NCH; ch++) {
                    const float* gch = fbn + (size_t)ch * HW;
                    #pragma unroll
                    for (int s = 0; s < 4; s++)
                        if (s < nslot)
                            cpa4(db + (unsigned)(tid + s * 256) * 16u + ch * 4u, gch + so[s]);
                }
                cpa_commit();
            }

            if (tid < NPOS) {
                const float4* P = &patch[buf][0];
                float a0 = 0.f, a1 = 0.f, a2 = 0.f, a3 = 0.f;
                #pragma unroll
                for (int k = 0; k < 4; k++) {
                    int   ay  = ryo[k];
                    float wyk = wy[k];
                    #pragma unroll
                    for (int l = 0; l < 4; l++) {
                        float wgt = wyk * wx[l];
                        float4 v  = P[ay + rxo[l]];
                        a0 = fmaf(wgt, v.x, a0);
                        a1 = fmaf(wgt, v.y, a1);
                        a2 = fmaf(wgt, v.z, a2);
                        a3 = fmaf(wgt, v.w, a3);
                    }
                }
                int c0 = ph * NCH;
                op[(c0 + 0) * NPOS] = a0;
                op[(c0 + 1) * NPOS] = a1;
                op[(c0 + 2) * NPOS] = a2;
                op[(c0 + 3) * NPOS] = a3;
            }
        }
    } else {
        if (tid >= NPOS) return;
        const float* fp = fp0;
        #pragma unroll 1
        for (int c = 0; c < CQ; c++) {
            float acc = 0.f;
            #pragma unroll
            for (int k = 0; k < 4; k++) {
                int   ay  = ryo[k] * W;
                float wyk = wy[k];
                #pragma unroll
                for (int l = 0; l < 4; l++)
                    acc = fmaf(wyk * wx[l], __ldg(fp + ay + rxo[l]), acc);
            }
            op[c * NPOS] = acc;
            fp += HW;
        }
    }
}

extern "C" void kernel_launch(void* const* d_in, const int* in_sizes, int n_in,
                              void* d_out, int out_size)
{
    const float* p4     = (const float*)d_in[0];
    const float* p8     = (const float*)d_in[1];
    const float* p16    = (const float*)d_in[2];
    const float* p32    = (const float*)d_in[3];
    const float* boxes  = (const float*)d_in[4];
    const float* scores = (const float*)d_in[5];
    float* out = (float*)d_out;

    nms_kernel<<<BB, NN>>>(boxes, scores, out);
    pool_kernel<<<BB * NN * 4, 256>>>(p4, p8, p16, p32, out);
}

// round 17
// speedup vs baseline: 1.2024x; 1.2024x over previous
#include <cuda_runtime.h>
#include <math.h>

#define BB 2
#define NN 512
#define CC 256
#define OUTSZ 14
#define POOL_PER_BOX (CC * OUTSZ * OUTSZ)   // 50176
#define NPOS (OUTSZ * OUTSZ)                // 196
#define CQ 64                               // channels per pool block (4-way split)
#define NCH 4                               // channels per phase (float4 interleave)
#define NPH (CQ / NCH)                      // 16 phases
#define PSZ 1024                            // patch elems per channel (worst ~991)

// Scratch (no allocations allowed)
__device__ float    g_verts[BB * NN * 4];   // original order
__device__ int      g_level[BB * NN];       // original order
__device__ int      g_keep [BB * NN];       // original order
__device__ float4   gs_box [BB * NN];       // sorted order (for scan tails)
__device__ int      gs_ord [BB * NN];       // sorted rank -> original index
__device__ unsigned g_maskw[BB * NN * 16];  // suppression matrix (sorted order)

// ---------------------------------------------------------------------------
// Kernel M: fused rank + ballot mask build. Grid = BB*64, 256 threads.
// Each block independently: loads 512 scores, computes verts/level/rank for
// 2 boxes per thread, scatters sorted arrays into smem, then builds its 8
// mask rows (warp per row) via ballot. Block (blk&63)==0 also publishes
// g_verts/g_level (original order) and gs_box/gs_ord (sorted) to global.
// Division-free IoU test (thr = 0.5): 2*inter > den.
// ---------------------------------------------------------------------------
__global__ __launch_bounds__(256) void nms_mask_kernel(const float* __restrict__ boxes,
                                                       const float* __restrict__ scores)
{
    const int blk   = blockIdx.x;
    const int b     = blk >> 6;             // 64 blocks per batch
    const int rbase = (blk & 63) << 3;      // 8 rows per block
    const bool pub  = ((blk & 63) == 0);    // publisher block for this batch
    const int tid   = threadIdx.x;
    const int wid   = tid >> 5;
    const int lane  = tid & 31;

    __shared__ float         sscore[NN];
    __shared__ float4        sbox[NN];
    __shared__ float         sarea[NN];
    __shared__ unsigned char slev[NN];

    // load scores
    #pragma unroll
    for (int q = 0; q < 2; q++) {
        int i = tid + q * 256;
        sscore[i] = scores[b * NN + i];
    }
    __syncthreads();

    // verts + level + counting-rank (2 boxes per thread)
    const float* bbp = boxes + (size_t)b * NN * 4;
    float x1v[2], y1v[2], x2v[2], y2v[2], msv[2];
    int   levv[2];
    #pragma unroll
    for (int q = 0; q < 2; q++) {
        int i = tid + q * 256;
        float cx = bbp[i * 4 + 0];
        float cy = bbp[i * 4 + 1];
        float w  = bbp[i * 4 + 2];
        float h  = bbp[i * 4 + 3];
        x1v[q] = cx - w * 0.5f;
        y1v[q] = cy - h * 0.5f;
        x2v[q] = cx + w * 0.5f;
        y2v[q] = cy + h * 0.5f;
        float lv = floorf(3.0f + log2f(sqrtf(w * h) / 224.0f));
        lv = fminf(fmaxf(lv, 1.0f), 4.0f);
        levv[q] = (int)lv;
        msv[q]  = sscore[i];
    }

    int r0 = 0, r1 = 0;
    const int i0 = tid, i1 = tid + 256;
    #pragma unroll 8
    for (int j = 0; j < NN; j++) {
        float sj = sscore[j];               // warp-broadcast LDS
        r0 += (sj > msv[0]) || (sj == msv[0] && j < i0);
        r1 += (sj > msv[1]) || (sj == msv[1] && j < i1);
    }

    #pragma unroll
    for (int q = 0; q < 2; q++) {
        int r = q ? r1 : r0;
        float4 bx = make_float4(x1v[q], y1v[q], x2v[q], y2v[q]);
        sbox [r] = bx;
        sarea[r] = (x2v[q] - x1v[q]) * (y2v[q] - y1v[q]);
        slev [r] = (unsigned char)levv[q];
        if (pub) {
            int i = q ? i1 : i0;
            int gi = b * NN + i;
            g_verts[gi * 4 + 0] = x1v[q];
            g_verts[gi * 4 + 1] = y1v[q];
            g_verts[gi * 4 + 2] = x2v[q];
            g_verts[gi * 4 + 3] = y2v[q];
            g_level[gi] = levv[q];
            gs_box[b * NN + r] = bx;
            gs_ord[b * NN + r] = i;
        }
    }
    __syncthreads();

    // mask rows: warp per row
    const int r = rbase + wid;
    float4 mb = sbox[r];
    float  marea = sarea[r];
    unsigned char mylev = slev[r];

    #pragma unroll
    for (int wq = 0; wq < 16; wq++) {
        int j = (wq << 5) + lane;
        float4 ob = sbox[j];
        float ix1 = fmaxf(mb.x, ob.x);
        float iy1 = fmaxf(mb.y, ob.y);
        float ix2 = fminf(mb.z, ob.z);
        float iy2 = fminf(mb.w, ob.w);
        float iw = fmaxf(ix2 - ix1, 0.0f);
        float ih = fmaxf(iy2 - iy1, 0.0f);
        float inter = iw * ih;
        float den = marea + sarea[j] - inter + 1e-9f;
        bool sup = (j > r) && (slev[j] == mylev) && (inter + inter > den);
        unsigned word = __ballot_sync(0xffffffffu, sup);
        if (lane == wq) g_maskw[(size_t)(b * NN + r) * 16 + wq] = word;
    }
}

// ---------------------------------------------------------------------------
// Kernel S: greedy scan + keep/out_boxes/keep-flag writes. Grid=BB, 512 thr.
// (Byte-identical logic to R14 — proven.)
// ---------------------------------------------------------------------------
__global__ __launch_bounds__(NN) void nms_scan_kernel(float* __restrict__ out)
{
    const int b   = blockIdx.x;
    const int tid = threadIdx.x;

    __shared__ unsigned smask[NN][16];
    __shared__ unsigned keepw_s[16];

    {
        const uint4* src = (const uint4*)&g_maskw[(size_t)b * NN * 16];
        uint4* dst = (uint4*)smask;
        #pragma unroll
        for (int i = tid; i < NN * 4; i += NN) dst[i] = src[i];
    }
    __syncthreads();

    if (tid < 32) {
        int wl = tid & 15;
        unsigned kw = 0xFFFFFFFFu;
        for (int wq = 0; wq < 16; wq++) {
            unsigned cur = __shfl_sync(0xffffffffu, kw, wq);
            while (cur) {
                int bq = __ffs(cur) - 1;
                int row = (wq << 5) + bq;
                unsigned mw = smask[row][wl];
                unsigned mq = smask[row][wq];
                cur &= ~(mq | (1u << bq));
                kw  &= ~mw;
            }
        }
        if (tid < 16) keepw_s[tid] = kw;
    }
    __syncthreads();

    int kept = (keepw_s[tid >> 5] >> (tid & 31)) & 1;
    int go = b * NN + gs_ord[b * NN + tid];
    g_keep[go] = kept;

    float4 sb = gs_box[b * NN + tid];
    float* ob = out + (size_t)BB * NN * POOL_PER_BOX;
    float* ok = ob + (size_t)BB * NN * 4;
    ob[go * 4 + 0] = kept ? sb.x : 0.0f;
    ob[go * 4 + 1] = kept ? sb.y : 0.0f;
    ob[go * 4 + 2] = kept ? sb.z : 0.0f;
    ob[go * 4 + 3] = kept ? sb.w : 0.0f;
    ok[go] = kept ? 1.0f : 0.0f;
}

// ---------------------------------------------------------------------------
// cp.async helpers
// ---------------------------------------------------------------------------
__device__ __forceinline__ void cpa4(unsigned dst_smem, const float* src) {
    asm volatile("cp.async.ca.shared.global [%0], [%1], 4;"
                 :: "r"(dst_smem), "l"(src) : "memory");
}
__device__ __forceinline__ void cpa_commit() {
    asm volatile("cp.async.commit_group;" ::: "memory");
}
__device__ __forceinline__ void cpa_wait0() {
    asm volatile("cp.async.wait_group 0;" ::: "memory");
}

// ---------------------------------------------------------------------------
// Kernel P: ROI align. Patch channel-interleaved as float4 -> each tap is one
// LDS.128 serving 4 channels. 4 blocks per box (64 channels each),
// double-buffered cp.async, one sync per phase. (Byte-identical to R14.)
// ---------------------------------------------------------------------------
__global__ __launch_bounds__(256, 4) void pool_kernel(const float* __restrict__ p4,
                                                      const float* __restrict__ p8,
                                                      const float* __restrict__ p16,
                                                      const float* __restrict__ p32,
                                                      float* __restrict__ out)
{
    const int bn      = blockIdx.x >> 2;
    const int quarter = blockIdx.x & 3;
    const int b       = bn / NN;
    const int tid     = threadIdx.x;

    float* o = out + (size_t)bn * POOL_PER_BOX + (size_t)quarter * CQ * NPOS;

    if (!g_keep[bn]) {
        float4* o4 = (float4*)o;
        float4 z = make_float4(0.f, 0.f, 0.f, 0.f);
        #pragma unroll 4
        for (int i = tid; i < CQ * NPOS / 4; i += 256) o4[i] = z;
        return;
    }

    const int lev = g_level[bn];
    const float* feat;
    int H;
    float stride;
    if (lev == 1)      { feat = p4;  H = 256; stride = 4.0f;  }
    else if (lev == 2) { feat = p8;  H = 128; stride = 8.0f;  }
    else if (lev == 3) { feat = p16; H = 64;  stride = 16.0f; }
    else               { feat = p32; H = 32;  stride = 32.0f; }
    const int W  = H;
    const int HW = H * W;

    float inv = 1.0f / stride;
    float rx1 = g_verts[bn * 4 + 0] * inv;
    float ry1 = g_verts[bn * 4 + 1] * inv;
    float rx2 = g_verts[bn * 4 + 2] * inv;
    float ry2 = g_verts[bn * 4 + 3] * inv;
    float bw = (rx2 - rx1) / (float)OUTSZ;
    float bh = (ry2 - ry1) / (float)OUTSZ;

    float xsf = fminf(fmaxf(rx1 + 0.25f  * bw, 0.0f), (float)W - 1.0f);
    float xsl = fminf(fmaxf(rx1 + 13.75f * bw, 0.0f), (float)W - 1.0f);
    float ysf = fminf(fmaxf(ry1 + 0.25f  * bh, 0.0f), (float)H - 1.0f);
    float ysl = fminf(fmaxf(ry1 + 13.75f * bh, 0.0f), (float)H - 1.0f);
    const int xmin  = (int)floorf(xsf);
    const int xmax  = min((int)floorf(xsl) + 1, W - 1);
    const int ymin  = (int)floorf(ysf);
    const int ymax  = min((int)floorf(ysl) + 1, H - 1);
    const int pcols = xmax - xmin + 1;
    const int prows = ymax - ymin + 1;
    const int pp    = prows * pcols;

    const int oy = (tid < NPOS) ? (tid / OUTSZ) : 0;
    const int ox = (tid < NPOS) ? (tid - oy * OUTSZ) : 0;

    int   rxo[4];
    float wx[4];
    #pragma unroll
    for (int j = 0; j < 2; j++) {
        float g  = ((float)(2 * ox + j) + 0.5f) * 0.5f;
        float xs = fminf(fmaxf(rx1 + g * bw, 0.0f), (float)W - 1.0f);
        float x0f = floorf(xs);
        int   x0  = (int)x0f;
        float lx  = xs - x0f;
        rxo[2 * j]     = x0;
        rxo[2 * j + 1] = min(x0 + 1, W - 1);
        wx[2 * j]      = 1.0f - lx;
        wx[2 * j + 1]  = lx;
    }
    int   ryo[4];
    float wy[4];
    #pragma unroll
    for (int j = 0; j < 2; j++) {
        float g  = ((float)(2 * oy + j) + 0.5f) * 0.5f;
        float ys = fminf(fmaxf(ry1 + g * bh, 0.0f), (float)H - 1.0f);
        float y0f = floorf(ys);
        int   y0  = (int)y0f;
        float ly  = ys - y0f;
        ryo[2 * j]     = y0;
        ryo[2 * j + 1] = min(y0 + 1, H - 1);
        wy[2 * j]      = 0.25f * (1.0f - ly);
        wy[2 * j + 1]  = 0.25f * ly;
    }

    const float* fp0 = feat + ((size_t)b * CC + (size_t)quarter * CQ) * HW;
    float* op = o + tid;

    if (pp <= PSZ) {
        __shared__ float4 patch[2][PSZ];

        #pragma unroll
        for (int k = 0; k < 4; k++) {
            rxo[k] -= xmin;
            ryo[k] = (ryo[k] - ymin) * pcols;
        }

        int so[4];
        #pragma unroll
        for (int s = 0; s < 4; s++) {
            int i = tid + s * 256;
            int py = i / pcols;
            int px = i - py * pcols;
            so[s] = py * W + px;
        }
        const int nslot = (pp > tid) ? ((pp - tid + 255) >> 8) : 0;
        const float* fb = fp0 + (size_t)ymin * W + xmin;
        const unsigned spbase = (unsigned)__cvta_generic_to_shared(&patch[0][0]);

        #pragma unroll
        for (int ch = 0; ch < NCH; ch++) {
            const float* gch = fb + (size_t)ch * HW;
            #pragma unroll
            for (int s = 0; s < 4; s++)
                if (s < nslot)
                    cpa4(spbase + (unsigned)(tid + s * 256) * 16u + ch * 4u, gch + so[s]);
        }
        cpa_commit();

        #pragma unroll 1
        for (int ph = 0; ph < NPH; ph++) {
            const int buf = ph & 1;
            cpa_wait0();
            __syncthreads();

            if (ph + 1 < NPH) {
                const float* fbn = fb + (size_t)(ph + 1) * NCH * HW;
                unsigned db = spbase + (unsigned)(buf ^ 1) * (PSZ * 16u);
                #pragma unroll
                for (int ch = 0; ch < NCH; ch++) {
                    const float* gch = fbn + (size_t)ch * HW;
                    #pragma unroll
                    for (int s = 0; s < 4; s++)
                        if (s < nslot)
                            cpa4(db + (unsigned)(tid + s * 256) * 16u + ch * 4u, gch + so[s]);
                }
                cpa_commit();
            }

            if (tid < NPOS) {
                const float4* P = &patch[buf][0];
                float a0 = 0.f, a1 = 0.f, a2 = 0.f, a3 = 0.f;
                #pragma unroll
                for (int k = 0; k < 4; k++) {
                    int   ay  = ryo[k];
                    float wyk = wy[k];
                    #pragma unroll
                    for (int l = 0; l < 4; l++) {
                        float wgt = wyk * wx[l];
                        float4 v  = P[ay + rxo[l]];
                        a0 = fmaf(wgt, v.x, a0);
                        a1 = fmaf(wgt, v.y, a1);
                        a2 = fmaf(wgt, v.z, a2);
                        a3 = fmaf(wgt, v.w, a3);
                    }
                }
                int c0 = ph * NCH;
                op[(c0 + 0) * NPOS] = a0;
                op[(c0 + 1) * NPOS] = a1;
                op[(c0 + 2) * NPOS] = a2;
                op[(c0 + 3) * NPOS] = a3;
            }
        }
    } else {
        if (tid >= NPOS) return;
        const float* fp = fp0;
        #pragma unroll 1
        for (int c = 0; c < CQ; c++) {
            float acc = 0.f;
            #pragma unroll
            for (int k = 0; k < 4; k++) {
                int   ay  = ryo[k] * W;
                float wyk = wy[k];
                #pragma unroll
                for (int l = 0; l < 4; l++)
                    acc = fmaf(wyk * wx[l], __ldg(fp + ay + rxo[l]), acc);
            }
            op[c * NPOS] = acc;
            fp += HW;
        }
    }
}

extern "C" void kernel_launch(void* const* d_in, const int* in_sizes, int n_in,
                              void* d_out, int out_size)
{
    const float* p4     = (const float*)d_in[0];
    const float* p8     = (const float*)d_in[1];
    const float* p16    = (const float*)d_in[2];
    const float* p32    = (const float*)d_in[3];
    const float* boxes  = (const float*)d_in[4];
    const float* scores = (const float*)d_in[5];
    float* out = (float*)d_out;

    nms_mask_kernel<<<BB * 64, 256>>>(boxes, scores);
    nms_scan_kernel<<<BB, NN>>>(out);
    pool_kernel<<<BB * NN * 4, 256>>>(p4, p8, p16, p32, out);
}